// round 14
// baseline (speedup 1.0000x reference)
#include <cuda_runtime.h>
#include <cuda_bf16.h>
#include <math.h>
#include <stdint.h>

// ---------------- problem constants ----------------
#define B_     32
#define N_     4096
#define F_     768
#define DIM_   256
#define H_     4
#define DH_    64
#define KSLOT_ 16
#define IH_    64
#define ITERS_ 3
#define EPSW_  1e-8f
#define SCALE_ 0.125f

// ---------------- scratch (device globals; no allocation) ----------------
__device__ __nv_bfloat16 g_xhi[100663296];   // [131072][768]
__device__ __nv_bfloat16 g_xlo[100663296];
__device__ __nv_bfloat16 g_wb_hi[393216];    // [512][768]
__device__ __nv_bfloat16 g_wb_lo[393216];
__device__ __nv_bfloat16 g_khi[33554432];    // [131072][256] bf16 split of k
__device__ __nv_bfloat16 g_klo[33554432];
__device__ __nv_bfloat16 g_vhi[33554432];
__device__ __nv_bfloat16 g_vlo[33554432];
__device__ __nv_bfloat16 g_qh[131072];       // [512][256]
__device__ __nv_bfloat16 g_ql[131072];
__device__ float g_vsum[B_*DIM_];
__device__ float g_slots[B_*KSLOT_*DIM_];
__device__ float g_S    [B_*IH_];
__device__ float g_upd  [B_*IH_*DH_];

extern __shared__ float dynsm[];

// ---------------- PTX helpers ----------------
__device__ __forceinline__ uint32_t smem_u32(const void* p) {
    uint32_t a;
    asm("{ .reg .u64 t; cvta.to.shared.u64 t, %1; cvt.u32.u64 %0, t; }" : "=r"(a) : "l"(p));
    return a;
}
#define CP_ASYNC16(dst, src) \
    asm volatile("cp.async.cg.shared.global [%0], [%1], 16;" :: "r"(dst), "l"(src))
#define CP_COMMIT()  asm volatile("cp.async.commit_group;")
#define CP_WAIT0()   asm volatile("cp.async.wait_group 0;")
#define CP_WAIT1()   asm volatile("cp.async.wait_group 1;")

#define LDSM4(r0, r1, r2, r3, a) \
    asm volatile("ldmatrix.sync.aligned.m8n8.x4.shared.b16 {%0,%1,%2,%3}, [%4];" \
        : "=r"(r0), "=r"(r1), "=r"(r2), "=r"(r3) : "r"(a))

#define MMA16816(c, a, b) \
    asm volatile("mma.sync.aligned.m16n8k16.row.col.f32.bf16.bf16.f32 " \
        "{%0,%1,%2,%3}, {%4,%5,%6,%7}, {%8,%9}, {%0,%1,%2,%3};" \
        : "+f"((c)[0]), "+f"((c)[1]), "+f"((c)[2]), "+f"((c)[3]) \
        : "r"((a)[0]), "r"((a)[1]), "r"((a)[2]), "r"((a)[3]), "r"((b)[0]), "r"((b)[1]))

#define MMA_TF32(c, a, b) \
    asm volatile("mma.sync.aligned.m16n8k8.row.col.f32.tf32.tf32.f32 " \
        "{%0,%1,%2,%3}, {%4,%5,%6,%7}, {%8,%9}, {%0,%1,%2,%3};" \
        : "+f"((c)[0]), "+f"((c)[1]), "+f"((c)[2]), "+f"((c)[3]) \
        : "r"((a)[0]), "r"((a)[1]), "r"((a)[2]), "r"((a)[3]), "r"((b)[0]), "r"((b)[1]))

__device__ __forceinline__ void tf32split(float x, uint32_t& hi, uint32_t& lo) {
    asm("cvt.rna.tf32.f32 %0, %1;" : "=r"(hi) : "f"(x));
    float r = x - __uint_as_float(hi);
    asm("cvt.rna.tf32.f32 %0, %1;" : "=r"(lo) : "f"(r));
}
// pack two floats into bf16x2 (c0 -> low half), return hi pair, output lo pair
__device__ __forceinline__ uint32_t packsplit2(float c0, float c1, uint32_t& lo) {
    uint32_t hi;
    asm("cvt.rn.bf16x2.f32 %0, %1, %2;" : "=r"(hi) : "f"(c1), "f"(c0));
    float h0 = __uint_as_float(hi << 16);
    float h1 = __uint_as_float(hi & 0xffff0000u);
    asm("cvt.rn.bf16x2.f32 %0, %1, %2;" : "=r"(lo) : "f"(c1 - h1), "f"(c0 - h0));
    return hi;
}

// ---------------- block reduce (256 threads) ----------------
__device__ __forceinline__ float2 blockReduceSum2(float a, float b) {
    __shared__ float sa[8], sb[8];
    int lane = threadIdx.x & 31, w = threadIdx.x >> 5;
#pragma unroll
    for (int o = 16; o; o >>= 1) {
        a += __shfl_down_sync(0xffffffffu, a, o);
        b += __shfl_down_sync(0xffffffffu, b, o);
    }
    if (lane == 0) { sa[w] = a; sb[w] = b; }
    __syncthreads();
    if (w == 0) {
        float aa = (lane < 8) ? sa[lane] : 0.f;
        float bb = (lane < 8) ? sb[lane] : 0.f;
#pragma unroll
        for (int o = 4; o; o >>= 1) {
            aa += __shfl_down_sync(0xffffffffu, aa, o);
            bb += __shfl_down_sync(0xffffffffu, bb, o);
        }
        if (lane == 0) { sa[0] = aa; sb[0] = bb; }
    }
    __syncthreads();
    float2 r = make_float2(sa[0], sb[0]);
    __syncthreads();
    return r;
}

// ---------------- K1: LayerNorm over 768 -> split bf16 hi/lo ----------------
__global__ __launch_bounds__(256) void ln_in_kernel(const float* __restrict__ x,
                                                    const float* __restrict__ g,
                                                    const float* __restrict__ bb) {
    size_t row = blockIdx.x;
    const float* xr = x + row * F_;
    int t = threadIdx.x;
    float v0 = xr[t], v1 = xr[t + 256], v2 = xr[t + 512];
    float2 r = blockReduceSum2(v0 + v1 + v2, v0 * v0 + v1 * v1 + v2 * v2);
    float mean = r.x * (1.f / 768.f);
    float var  = r.y * (1.f / 768.f) - mean * mean;
    float inv  = rsqrtf(var + 1e-5f);
    __nv_bfloat16* oh = g_xhi + row * F_;
    __nv_bfloat16* ol = g_xlo + row * F_;
#pragma unroll
    for (int e = 0; e < 3; e++) {
        int c = t + 256 * e;
        float vv = (e == 0 ? v0 : (e == 1 ? v1 : v2));
        float y = (vv - mean) * inv * g[c] + bb[c];
        __nv_bfloat16 h = __float2bfloat16(y);
        oh[c] = h;
        ol[c] = __float2bfloat16(y - __bfloat162float(h));
    }
}

// ---- wconv: weight split-convert + zero vsum/S/upd (512 blocks) ----
__global__ __launch_bounds__(256) void wconv_kernel(const float* __restrict__ Wk,
                                                    const float* __restrict__ Wv) {
    int bidx = blockIdx.x, t = threadIdx.x;
#pragma unroll
    for (int e = 0; e < 3; e++) {
        int idx = bidx * 768 + e * 256 + t;
        float w = (idx < 196608) ? Wk[idx] : Wv[idx - 196608];
        __nv_bfloat16 h = __float2bfloat16(w);
        g_wb_hi[idx] = h;
        g_wb_lo[idx] = __float2bfloat16(w - __bfloat162float(h));
    }
    g_upd[bidx * 256 + t] = 0.f;
    if (t < 4) g_S[bidx * 4 + t] = 0.f;
    if (bidx < 32) g_vsum[bidx * 256 + t] = 0.f;
}

// ---- slotq0: iter-0 slot LN + q projection -> bf16 split (512 blocks) ----
__global__ __launch_bounds__(256) void slotq0_kernel(const float* __restrict__ lsg,
                                                     const float* __restrict__ lsb,
                                                     const float* __restrict__ Wq) {
    __shared__ float sn[256];
    int row = blockIdx.x, t = threadIdx.x;
    float sv = g_slots[row * 256 + t];
    float2 r = blockReduceSum2(sv, sv * sv);
    float mean = r.x * (1.f / 256.f);
    float var  = r.y * (1.f / 256.f) - mean * mean;
    float inv  = rsqrtf(var + 1e-5f);
    sn[t] = (sv - mean) * inv * lsg[t] + lsb[t];
    __syncthreads();
    const float4* w4 = (const float4*)(Wq + (size_t)t * 256);
    float acc = 0.f;
#pragma unroll 8
    for (int c = 0; c < 64; c++) {
        float4 w = w4[c];
        acc += w.x * sn[4 * c] + w.y * sn[4 * c + 1] + w.z * sn[4 * c + 2] + w.w * sn[4 * c + 3];
    }
    float qv = acc * SCALE_;
    __nv_bfloat16 h = __float2bfloat16(qv);
    g_qh[row * 256 + t] = h;
    g_ql[row * 256 + t] = __float2bfloat16(qv - __bfloat162float(h));
}

// ---------------- split-bf16 mma.sync projection GEMM (3-stage) ----------------
#define PSTG   65536
#define PROJ_SMEM (3 * PSTG)

__device__ __forceinline__ void proj_fill_async(uint32_t stg, int kt, size_t m0,
                                                int n0, int t) {
#pragma unroll
    for (int i = 0; i < 4; i++) {
        int idx = t + 256 * i;
        int row = idx >> 3, c = idx & 7;
        uint32_t off = row * 128 + ((c ^ (row & 7)) << 4);
        size_t aoff = ((m0 + row) * 768 + (size_t)kt * 64 + c * 8) * 2;
        size_t boff = (((size_t)(n0 + row)) * 768 + (size_t)kt * 64 + c * 8) * 2;
        CP_ASYNC16(stg + off,         (const char*)g_xhi   + aoff);
        CP_ASYNC16(stg + 16384 + off, (const char*)g_xlo   + aoff);
        CP_ASYNC16(stg + 32768 + off, (const char*)g_wb_hi + boff);
        CP_ASYNC16(stg + 49152 + off, (const char*)g_wb_lo + boff);
    }
}

__global__ __launch_bounds__(256) void proj_mma_kernel() {
    uint32_t base = smem_u32(dynsm);
    const int t = threadIdx.x;
    const int lane = t & 31, wid = t >> 5;
    const int wm = wid & 1, wn = wid >> 1;
    const int bx = blockIdx.x;
    const size_t m0 = (size_t)blockIdx.y * 128;
    const int n0 = bx * 128;

    float c[4][4][4];
#pragma unroll
    for (int mi = 0; mi < 4; mi++)
#pragma unroll
        for (int ni = 0; ni < 4; ni++)
#pragma unroll
            for (int e = 0; e < 4; e++) c[mi][ni][e] = 0.f;

    const int g = lane >> 3, rin = lane & 7;

    proj_fill_async(base, 0, m0, n0, t);
    CP_COMMIT();
    proj_fill_async(base + PSTG, 1, m0, n0, t);
    CP_COMMIT();

    for (int kt = 0; kt < 12; kt++) {
        if (kt + 2 < 12) CP_WAIT1(); else CP_WAIT0();
        __syncthreads();
        if (kt + 2 < 12) {
            proj_fill_async(base + (uint32_t)((kt + 2) % 3) * PSTG, kt + 2, m0, n0, t);
            CP_COMMIT();
        }
        uint32_t cur = base + (uint32_t)(kt % 3) * PSTG;

#pragma unroll
        for (int ks = 0; ks < 4; ks++) {
            uint32_t aHi[4][4], aLo[4][4], bHi[4][2], bLo[4][2];
#pragma unroll
            for (int mi = 0; mi < 4; mi++) {
                int row = wm * 64 + mi * 16 + (g & 1) * 8 + rin;
                int cc = ks * 2 + (g >> 1);
                uint32_t ad = cur + row * 128 + ((cc ^ (row & 7)) << 4);
                LDSM4(aHi[mi][0], aHi[mi][1], aHi[mi][2], aHi[mi][3], ad);
                LDSM4(aLo[mi][0], aLo[mi][1], aLo[mi][2], aLo[mi][3], ad + 16384);
            }
#pragma unroll
            for (int bi = 0; bi < 2; bi++) {
                int nr = wn * 32 + bi * 16 + (g >> 1) * 8 + rin;
                int cc = ks * 2 + (g & 1);
                uint32_t bd = cur + 32768 + nr * 128 + ((cc ^ (nr & 7)) << 4);
                uint32_t r0, r1, r2, r3;
                LDSM4(r0, r1, r2, r3, bd);
                bHi[bi * 2][0] = r0; bHi[bi * 2][1] = r1;
                bHi[bi * 2 + 1][0] = r2; bHi[bi * 2 + 1][1] = r3;
                LDSM4(r0, r1, r2, r3, bd + 16384);
                bLo[bi * 2][0] = r0; bLo[bi * 2][1] = r1;
                bLo[bi * 2 + 1][0] = r2; bLo[bi * 2 + 1][1] = r3;
            }
#pragma unroll
            for (int mi = 0; mi < 4; mi++)
#pragma unroll
                for (int ni = 0; ni < 4; ni++) {
                    MMA16816(c[mi][ni], aHi[mi], bHi[ni]);
                    MMA16816(c[mi][ni], aHi[mi], bLo[ni]);
                    MMA16816(c[mi][ni], aLo[mi], bHi[ni]);
                }
        }
    }

    // epilogue: bf16 hi/lo split stores
    __nv_bfloat16* oh = (bx < 2) ? g_khi : g_vhi;
    __nv_bfloat16* ol = (bx < 2) ? g_klo : g_vlo;
    int cb = (bx & 1) * 128 + wn * 32 + (lane & 3) * 2;
#pragma unroll
    for (int mi = 0; mi < 4; mi++) {
        size_t r0 = m0 + wm * 64 + mi * 16 + (lane >> 2);
#pragma unroll
        for (int ni = 0; ni < 4; ni++) {
            int col = cb + ni * 8;
            uint32_t lo0, lo1;
            uint32_t hi0 = packsplit2(c[mi][ni][0], c[mi][ni][1], lo0);
            uint32_t hi1 = packsplit2(c[mi][ni][2], c[mi][ni][3], lo1);
            *(uint32_t*)(oh + r0 * 256 + col)       = hi0;
            *(uint32_t*)(ol + r0 * 256 + col)       = lo0;
            *(uint32_t*)(oh + (r0 + 8) * 256 + col) = hi1;
            *(uint32_t*)(ol + (r0 + 8) * 256 + col) = lo1;
        }
    }

    // fused vsum for V tiles
    if (bx >= 2) {
        int b = (int)(m0 >> 12);
#pragma unroll
        for (int ni = 0; ni < 4; ni++) {
            float s0 = 0.f, s1 = 0.f;
#pragma unroll
            for (int mi = 0; mi < 4; mi++) {
                s0 += c[mi][ni][0] + c[mi][ni][2];
                s1 += c[mi][ni][1] + c[mi][ni][3];
            }
#pragma unroll
            for (int o = 16; o >= 4; o >>= 1) {
                s0 += __shfl_down_sync(0xffffffffu, s0, o);
                s1 += __shfl_down_sync(0xffffffffu, s1, o);
            }
            if (lane < 4) {
                int col = (bx & 1) * 128 + wn * 32 + lane * 2 + ni * 8;
                atomicAdd(&g_vsum[b * 256 + col], s0);
                atomicAdd(&g_vsum[b * 256 + col + 1], s1);
            }
        }
    }
}

// ---------------- fused attention: bf16-MMA dots + softmax + S + tf32-MMA updates ----
// grid (128 j-tiles of 32, 32 b), 256 threads, 2 CTAs/SM.
// smem floats: q bf16 (4864 fl) | kv region (16640 fl) | dsT (2176) | red (256)
#define NJ_ 32
#define ATTN_SMEM 95744
__global__ __launch_bounds__(256, 2) void attn_kernel(float* __restrict__ attn_out) {
    __nv_bfloat16* qh_b = (__nv_bfloat16*)dynsm;               // [64 ih][76]
    __nv_bfloat16* ql_b = qh_b + 64 * 76;
    float* kvreg = dynsm + 4864;                               // 16640 floats
    __nv_bfloat16* kh_b = (__nv_bfloat16*)kvreg;               // [32 j][264]
    __nv_bfloat16* kl_b = kh_b + 32 * 264;
    float* vh_f = kvreg;                                       // [32 j][260]
    float* vl_f = kvreg + 32 * 260;
    float* dsT = dynsm + 4864 + 16640;                         // [32 j][68 ih]
    float* red = dsT + 32 * 68;                                // [8][32]/[4][64]
    int b = blockIdx.y, jt = blockIdx.x, t = threadIdx.x;
    int lane = t & 31, wid = t >> 5;
    int grp4 = lane >> 2, tg4 = lane & 3;

    // load q (bf16 split) into [ih][76] layout
    {
        const uint32_t* qhg = (const uint32_t*)(g_qh + (size_t)b * KSLOT_ * DIM_);
        const uint32_t* qlg = (const uint32_t*)(g_ql + (size_t)b * KSLOT_ * DIM_);
        for (int idx = t; idx < 2048; idx += 256) {
            int i = idx >> 7, cp = idx & 127;
            int c2 = cp * 2;
            int ih = i * 4 + (c2 >> 6), col = c2 & 63;
            *(uint32_t*)(qh_b + ih * 76 + col) = qhg[idx];
            *(uint32_t*)(ql_b + ih * 76 + col) = qlg[idx];
        }
    }
    // load k (bf16 split) into [j][264]
    {
        size_t base = ((size_t)b * N_ + jt * NJ_) * DIM_;
        const uint32_t* khg = (const uint32_t*)(g_khi + base);
        const uint32_t* klg = (const uint32_t*)(g_klo + base);
        for (int idx = t; idx < 4096; idx += 256) {
            int j = idx >> 7, cp = idx & 127;
            *(uint32_t*)(kh_b + j * 264 + cp * 2) = khg[j * 128 + cp];
            *(uint32_t*)(kl_b + j * 264 + cp * 2) = klg[j * 128 + cp];
        }
    }
    __syncthreads();

    // -------- dots via bf16 split MMA m16n8k16: warp: head h = wid>>1, j-half jh = wid&1
    {
        int h = wid >> 1, jh = wid & 1;
        float c[2][4];
#pragma unroll
        for (int f = 0; f < 2; f++)
#pragma unroll
            for (int e = 0; e < 4; e++) c[f][e] = 0.f;

        int ra = (grp4 * 4 + h) * 76, rb = ((grp4 + 8) * 4 + h) * 76;
#pragma unroll
        for (int k16 = 0; k16 < 4; k16++) {
            int k0 = k16 * 16 + tg4 * 2;
            uint32_t ah[4], al[4];
            ah[0] = *(const uint32_t*)(qh_b + ra + k0);
            ah[1] = *(const uint32_t*)(qh_b + rb + k0);
            ah[2] = *(const uint32_t*)(qh_b + ra + k0 + 8);
            ah[3] = *(const uint32_t*)(qh_b + rb + k0 + 8);
            al[0] = *(const uint32_t*)(ql_b + ra + k0);
            al[1] = *(const uint32_t*)(ql_b + rb + k0);
            al[2] = *(const uint32_t*)(ql_b + ra + k0 + 8);
            al[3] = *(const uint32_t*)(ql_b + rb + k0 + 8);
#pragma unroll
            for (int n8 = 0; n8 < 2; n8++) {
                int j = jh * 16 + n8 * 8 + grp4;
                const __nv_bfloat16* krh = kh_b + j * 264 + h * 64;
                const __nv_bfloat16* krl = kl_b + j * 264 + h * 64;
                uint32_t bh[2], bl[2];
                bh[0] = *(const uint32_t*)(krh + k0);
                bh[1] = *(const uint32_t*)(krh + k0 + 8);
                bl[0] = *(const uint32_t*)(krl + k0);
                bl[1] = *(const uint32_t*)(krl + k0 + 8);
                MMA16816(c[n8], ah, bh);
                MMA16816(c[n8], ah, bl);
                MMA16816(c[n8], al, bh);
            }
        }
#pragma unroll
        for (int n8 = 0; n8 < 2; n8++) {
            int jb = jh * 16 + n8 * 8 + tg4 * 2;
            dsT[jb * 68 + grp4 * 4 + h]             = c[n8][0];
            dsT[(jb + 1) * 68 + grp4 * 4 + h]       = c[n8][1];
            dsT[jb * 68 + (grp4 + 8) * 4 + h]       = c[n8][2];
            dsT[(jb + 1) * 68 + (grp4 + 8) * 4 + h] = c[n8][3];
        }
    }
    __syncthreads();

    // joint softmax over 64 (slot,head), per column j. 8 groups x 8 rows.
    {
        int j = t & 31, grp = t >> 5;
        float* row = dsT + j * 68 + grp * 8;
        float mx = -1e30f;
#pragma unroll
        for (int k2 = 0; k2 < 8; k2++) mx = fmaxf(mx, row[k2]);
        red[grp * 32 + j] = mx;
        __syncthreads();
        mx = red[j];
#pragma unroll
        for (int g2 = 1; g2 < 8; g2++) mx = fmaxf(mx, red[g2 * 32 + j]);
        __syncthreads();
        float sum = 0.f;
#pragma unroll
        for (int k2 = 0; k2 < 8; k2++) {
            float e = expf(row[k2] - mx);
            row[k2] = e;
            sum += e;
        }
        red[grp * 32 + j] = sum;
        __syncthreads();
        sum = red[j];
#pragma unroll
        for (int g2 = 1; g2 < 8; g2++) sum += red[g2 * 32 + j];
        float inv = 1.f / sum;
#pragma unroll
        for (int k2 = 0; k2 < 8; k2++) row[k2] *= inv;
    }
    __syncthreads();

    // S row sums -> atomic
    {
        int ih2 = t & 63, jq = t >> 6;
        float s = 0.f;
#pragma unroll
        for (int k2 = 0; k2 < 8; k2++) s += dsT[(jq * 8 + k2) * 68 + ih2];
        red[jq * 64 + ih2] = s;
    }
    __syncthreads();
    if (t < 64) atomicAdd(&g_S[b * IH_ + t], red[t] + red[64 + t] + red[128 + t] + red[192 + t]);

    // attn_out on last iteration
    if (attn_out) {
        for (int idx = t; idx < 512; idx += 256) {
            int i2 = idx >> 5, jl = idx & 31;
            float4 vv = *(const float4*)(dsT + jl * 68 + i2 * 4);
            attn_out[((size_t)b * KSLOT_ + i2) * N_ + jt * NJ_ + jl] =
                0.25f * (vv.x + vv.y + vv.z + vv.w);
        }
    }
    __syncthreads();

    // load v (bf16 split -> f32 smem), overwrites k region
    {
        size_t base = ((size_t)b * N_ + jt * NJ_) * DIM_;
        const uint32_t* vhg = (const uint32_t*)(g_vhi + base);
        const uint32_t* vlg = (const uint32_t*)(g_vlo + base);
        for (int idx = t; idx < 4096; idx += 256) {
            int j = idx >> 7, cp = idx & 127;
            uint32_t wh = vhg[j * 128 + cp];
            uint32_t wl = vlg[j * 128 + cp];
            *(float2*)(vh_f + j * 260 + cp * 2) =
                make_float2(__uint_as_float(wh << 16), __uint_as_float(wh & 0xffff0000u));
            *(float2*)(vl_f + j * 260 + cp * 2) =
                make_float2(__uint_as_float(wl << 16), __uint_as_float(wl & 0xffff0000u));
        }
    }
    __syncthreads();

    // -------- updates via tf32 MMA: warp: head h = wid>>1, d-half dh = wid&1
    {
        int h = wid >> 1, dh = wid & 1;
        float c[4][4];
#pragma unroll
        for (int f = 0; f < 4; f++)
#pragma unroll
            for (int e = 0; e < 4; e++) c[f][e] = 0.f;

#pragma unroll
        for (int k8 = 0; k8 < 4; k8++) {
            int j0 = k8 * 8 + tg4;
            float a0f = dsT[j0 * 68 + grp4 * 4 + h];
            float a1f = dsT[j0 * 68 + (grp4 + 8) * 4 + h];
            float a2f = dsT[(j0 + 4) * 68 + grp4 * 4 + h];
            float a3f = dsT[(j0 + 4) * 68 + (grp4 + 8) * 4 + h];
            uint32_t ah[4], al[4];
            tf32split(a0f, ah[0], al[0]);
            tf32split(a1f, ah[1], al[1]);
            tf32split(a2f, ah[2], al[2]);
            tf32split(a3f, ah[3], al[3]);
#pragma unroll
            for (int n8 = 0; n8 < 4; n8++) {
                int d = h * 64 + dh * 32 + n8 * 8 + grp4;
                uint32_t bh[2], bl[2];
                bh[0] = __float_as_uint(vh_f[j0 * 260 + d]);
                bh[1] = __float_as_uint(vh_f[(j0 + 4) * 260 + d]);
                bl[0] = __float_as_uint(vl_f[j0 * 260 + d]);
                bl[1] = __float_as_uint(vl_f[(j0 + 4) * 260 + d]);
                MMA_TF32(c[n8], ah, bh);
                MMA_TF32(c[n8], ah, bl);
                MMA_TF32(c[n8], al, bh);
            }
        }
#pragma unroll
        for (int n8 = 0; n8 < 4; n8++) {
            int dcol = dh * 32 + n8 * 8 + tg4 * 2;
            size_t base0 = ((size_t)b * KSLOT_ + grp4) * 4 + h;
            size_t base8 = ((size_t)b * KSLOT_ + grp4 + 8) * 4 + h;
            atomicAdd(&g_upd[base0 * DH_ + dcol],     c[n8][0]);
            atomicAdd(&g_upd[base0 * DH_ + dcol + 1], c[n8][1]);
            atomicAdd(&g_upd[base8 * DH_ + dcol],     c[n8][2]);
            atomicAdd(&g_upd[base8 * DH_ + dcol + 1], c[n8][3]);
        }
    }
}

// ---------------- GRU (8 rows per block) ----------------
__global__ __launch_bounds__(256) void gru_kernel(const float* __restrict__ w_ih,
                                                  const float* __restrict__ w_hh,
                                                  const float* __restrict__ b_ih,
                                                  const float* __restrict__ b_hh) {
    __shared__ float u[8][256];
    __shared__ float hp[8][256];
    int row0 = blockIdx.x * 8, t = threadIdx.x;
    int b = row0 >> 4;
#pragma unroll
    for (int r = 0; r < 8; r++) {
        int row = row0 + r;
        int ih = (row & 15) * 4 + (t >> 6);
        float upd = g_upd[(b * IH_ + ih) * DH_ + (t & 63)];
        float Sv  = g_S[b * IH_ + ih];
        u[r][t]  = (upd + EPSW_ * g_vsum[b * 256 + t]) / (Sv + (float)N_ * EPSW_);
        hp[r][t] = g_slots[(size_t)row * 256 + t];
    }
    __syncthreads();

    float s0a[8], s1a[8], gi2[8], gh2[8];
#pragma unroll
    for (int r = 0; r < 8; r++) { s0a[r] = 0.f; s1a[r] = 0.f; gi2[r] = 0.f; gh2[r] = 0.f; }

    const float4* wi0 = (const float4*)(w_ih + (size_t)t * 256);
    const float4* wi1 = (const float4*)(w_ih + (size_t)(256 + t) * 256);
    const float4* wi2 = (const float4*)(w_ih + (size_t)(512 + t) * 256);
    const float4* wh0 = (const float4*)(w_hh + (size_t)t * 256);
    const float4* wh1 = (const float4*)(w_hh + (size_t)(256 + t) * 256);
    const float4* wh2 = (const float4*)(w_hh + (size_t)(512 + t) * 256);

    for (int c = 0; c < 64; c++) {
        float4 a0 = wi0[c], a1 = wi1[c], a2 = wi2[c];
        float4 h0 = wh0[c], h1v = wh1[c], h2 = wh2[c];
#pragma unroll
        for (int r = 0; r < 8; r++) {
            float4 uu = *(const float4*)&u[r][4 * c];
            float4 hh = *(const float4*)&hp[r][4 * c];
            s0a[r] += a0.x * uu.x + a0.y * uu.y + a0.z * uu.z + a0.w * uu.w
                    + h0.x * hh.x + h0.y * hh.y + h0.z * hh.z + h0.w * hh.w;
            s1a[r] += a1.x * uu.x + a1.y * uu.y + a1.z * uu.z + a1.w * uu.w
                    + h1v.x * hh.x + h1v.y * hh.y + h1v.z * hh.z + h1v.w * hh.w;
            gi2[r] += a2.x * uu.x + a2.y * uu.y + a2.z * uu.z + a2.w * uu.w;
            gh2[r] += h2.x * hh.x + h2.y * hh.y + h2.z * hh.z + h2.w * hh.w;
        }
    }
    float bi0 = b_ih[t] + b_hh[t];
    float bi1 = b_ih[256 + t] + b_hh[256 + t];
    float bi2 = b_ih[512 + t], bh2 = b_hh[512 + t];
#pragma unroll
    for (int r = 0; r < 8; r++) {
        float rg = 1.f / (1.f + expf(-(s0a[r] + bi0)));
        float z  = 1.f / (1.f + expf(-(s1a[r] + bi1)));
        float n  = tanhf(gi2[r] + bi2 + rg * (gh2[r] + bh2));
        g_slots[(size_t)(row0 + r) * 256 + t] = (1.f - z) * n + z * hp[r][t];
    }
}

// ---------------- FF (8 rows per block) + next-iter slot_q + zeroing ----------------
__global__ __launch_bounds__(256) void ff_kernel(const float* __restrict__ g,
                                                 const float* __restrict__ bb,
                                                 const float* __restrict__ W1,
                                                 const float* __restrict__ b1,
                                                 const float* __restrict__ W2,
                                                 const float* __restrict__ b2,
                                                 const float* __restrict__ lsg,
                                                 const float* __restrict__ lsb,
                                                 const float* __restrict__ Wq,
                                                 int doq) {
    __shared__ float h1[8][256];
    __shared__ float a_s[8][1024];
    int row0 = blockIdx.x * 8, t = threadIdx.x;
    int w = t >> 5, l = t & 31;

    {   // LN (ff)
        int row = row0 + w;
        const float* sp = g_slots + (size_t)row * 256;
        float4 x0 = *(const float4*)(sp + l * 8);
        float4 x1 = *(const float4*)(sp + l * 8 + 4);
        float s = x0.x + x0.y + x0.z + x0.w + x1.x + x1.y + x1.z + x1.w;
        float q = x0.x * x0.x + x0.y * x0.y + x0.z * x0.z + x0.w * x0.w
                + x1.x * x1.x + x1.y * x1.y + x1.z * x1.z + x1.w * x1.w;
#pragma unroll
        for (int o = 16; o; o >>= 1) {
            s += __shfl_xor_sync(0xffffffffu, s, o);
            q += __shfl_xor_sync(0xffffffffu, q, o);
        }
        float mean = s * (1.f / 256.f);
        float var  = q * (1.f / 256.f) - mean * mean;
        float inv  = rsqrtf(var + 1e-5f);
        int c0 = l * 8;
        float xv[8] = {x0.x, x0.y, x0.z, x0.w, x1.x, x1.y, x1.z, x1.w};
#pragma unroll
        for (int e = 0; e < 8; e++)
            h1[w][c0 + e] = (xv[e] - mean) * inv * g[c0 + e] + bb[c0 + e];
    }
    __syncthreads();

    float acc[4][8];
#pragma unroll
    for (int m = 0; m < 4; m++)
#pragma unroll
        for (int r = 0; r < 8; r++) acc[m][r] = 0.f;

    const float4* w1p0 = (const float4*)(W1 + (size_t)t * 256);
    const float4* w1p1 = (const float4*)(W1 + (size_t)(t + 256) * 256);
    const float4* w1p2 = (const float4*)(W1 + (size_t)(t + 512) * 256);
    const float4* w1p3 = (const float4*)(W1 + (size_t)(t + 768) * 256);
    for (int c = 0; c < 64; c++) {
        float4 wv0 = w1p0[c], wv1 = w1p1[c], wv2 = w1p2[c], wv3 = w1p3[c];
#pragma unroll
        for (int r = 0; r < 8; r++) {
            float4 hh = *(const float4*)&h1[r][4 * c];
            acc[0][r] += wv0.x * hh.x + wv0.y * hh.y + wv0.z * hh.z + wv0.w * hh.w;
            acc[1][r] += wv1.x * hh.x + wv1.y * hh.y + wv1.z * hh.z + wv1.w * hh.w;
            acc[2][r] += wv2.x * hh.x + wv2.y * hh.y + wv2.z * hh.z + wv2.w * hh.w;
            acc[3][r] += wv3.x * hh.x + wv3.y * hh.y + wv3.z * hh.z + wv3.w * hh.w;
        }
    }
#pragma unroll
    for (int m = 0; m < 4; m++) {
        float bv = b1[m * 256 + t];
#pragma unroll
        for (int r = 0; r < 8; r++) {
            float v = acc[m][r] + bv;
            a_s[r][m * 256 + t] = 0.5f * v * (1.f + erff(v * 0.70710678118654752f));
        }
    }
    __syncthreads();

    float o[8];
#pragma unroll
    for (int r = 0; r < 8; r++) o[r] = 0.f;
    const float4* w2p = (const float4*)(W2 + (size_t)t * 1024);
    for (int c = 0; c < 256; c++) {
        float4 wv = w2p[c];
#pragma unroll
        for (int r = 0; r < 8; r++) {
            float4 aa = *(const float4*)&a_s[r][4 * c];
            o[r] += wv.x * aa.x + wv.y * aa.y + wv.z * aa.z + wv.w * aa.w;
        }
    }
    float bt = b2[t];
    __syncthreads();
#pragma unroll
    for (int r = 0; r < 8; r++) {
        float fin = g_slots[(size_t)(row0 + r) * 256 + t] + o[r] + bt;
        g_slots[(size_t)(row0 + r) * 256 + t] = fin;
        a_s[r][t] = fin;
    }
    __syncthreads();

    if (doq) {
        {   // LN (slots) for q
            float4 x0 = *(const float4*)&a_s[w][l * 8];
            float4 x1 = *(const float4*)&a_s[w][l * 8 + 4];
            float s = x0.x + x0.y + x0.z + x0.w + x1.x + x1.y + x1.z + x1.w;
            float q = x0.x * x0.x + x0.y * x0.y + x0.z * x0.z + x0.w * x0.w
                    + x1.x * x1.x + x1.y * x1.y + x1.z * x1.z + x1.w * x1.w;
#pragma unroll
            for (int oo = 16; oo; oo >>= 1) {
                s += __shfl_xor_sync(0xffffffffu, s, oo);
                q += __shfl_xor_sync(0xffffffffu, q, oo);
            }
            float mean = s * (1.f / 256.f);
            float var  = q * (1.f / 256.f) - mean * mean;
            float inv  = rsqrtf(var + 1e-5f);
            int c0 = l * 8;
            float xv[8] = {x0.x, x0.y, x0.z, x0.w, x1.x, x1.y, x1.z, x1.w};
#pragma unroll
            for (int e = 0; e < 8; e++)
                h1[w][c0 + e] = (xv[e] - mean) * inv * lsg[c0 + e] + lsb[c0 + e];
        }
        __syncthreads();

        float qa[8];
#pragma unroll
        for (int r = 0; r < 8; r++) qa[r] = 0.f;
        const float4* wq4 = (const float4*)(Wq + (size_t)t * 256);
        for (int c = 0; c < 64; c++) {
            float4 wv = wq4[c];
#pragma unroll
            for (int r = 0; r < 8; r++) {
                float4 ss = *(const float4*)&h1[r][4 * c];
                qa[r] += wv.x * ss.x + wv.y * ss.y + wv.z * ss.z + wv.w * ss.w;
            }
        }
#pragma unroll
        for (int r = 0; r < 8; r++) {
            float qv = qa[r] * SCALE_;
            __nv_bfloat16 h = __float2bfloat16(qv);
            g_qh[(size_t)(row0 + r) * 256 + t] = h;
            g_ql[(size_t)(row0 + r) * 256 + t] = __float2bfloat16(qv - __bfloat162float(h));
        }

#pragma unroll
        for (int e = 0; e < 8; e++)
            g_upd[blockIdx.x * 2048 + e * 256 + t] = 0.f;
        if (t < 32) g_S[blockIdx.x * 32 + t] = 0.f;
    }
}

// ---------------- launch ----------------
extern "C" void kernel_launch(void* const* d_in, const int* in_sizes, int n_in,
                              void* d_out, int out_size) {
    const float* inputs  = (const float*)d_in[0];
    const float* cond    = (const float*)d_in[1];
    const float* to_q_w  = (const float*)d_in[2];
    const float* to_k_w  = (const float*)d_in[3];
    const float* to_v_w  = (const float*)d_in[4];
    const float* w_ih    = (const float*)d_in[5];
    const float* w_hh    = (const float*)d_in[6];
    const float* b_ih    = (const float*)d_in[7];
    const float* b_hh    = (const float*)d_in[8];
    const float* ln_in_g = (const float*)d_in[9];
    const float* ln_in_b = (const float*)d_in[10];
    const float* ln_s_g  = (const float*)d_in[11];
    const float* ln_s_b  = (const float*)d_in[12];
    const float* ff_g    = (const float*)d_in[13];
    const float* ff_b    = (const float*)d_in[14];
    const float* ff_w1   = (const float*)d_in[15];
    const float* ff_b1   = (const float*)d_in[16];
    const float* ff_w2   = (const float*)d_in[17];
    const float* ff_b2   = (const float*)d_in[18];

    float* out_slots = (float*)d_out;
    float* out_attn  = out_slots + (size_t)B_ * KSLOT_ * DIM_;

    void* pSlots = nullptr;
    cudaGetSymbolAddress(&pSlots, g_slots);

    cudaFuncSetAttribute(attn_kernel, cudaFuncAttributeMaxDynamicSharedMemorySize, ATTN_SMEM);
    cudaFuncSetAttribute(proj_mma_kernel, cudaFuncAttributeMaxDynamicSharedMemorySize, PROJ_SMEM);

    cudaMemcpyAsync(pSlots, cond, (size_t)B_ * KSLOT_ * DIM_ * sizeof(float),
                    cudaMemcpyDeviceToDevice, 0);

    // launch order: 4th kernel = proj_mma (ncu capture target this round)
    ln_in_kernel<<<B_ * N_, 256>>>(inputs, ln_in_g, ln_in_b);                 // 1
    wconv_kernel<<<512, 256>>>(to_k_w, to_v_w);                               // 2
    slotq0_kernel<<<512, 256>>>(ln_s_g, ln_s_b, to_q_w);                      // 3
    proj_mma_kernel<<<dim3(4, 1024), 256, PROJ_SMEM>>>();                     // 4

    for (int it = 0; it < ITERS_; it++) {
        attn_kernel<<<dim3(128, B_), 256, ATTN_SMEM>>>(it == ITERS_ - 1 ? out_attn : (float*)nullptr);
        gru_kernel<<<64, 256>>>(w_ih, w_hh, b_ih, b_hh);
        ff_kernel<<<64, 256>>>(ff_g, ff_b, ff_w1, ff_b1, ff_w2, ff_b2,
                               ln_s_g, ln_s_b, to_q_w, it < ITERS_ - 1 ? 1 : 0);
    }
    cudaMemcpyAsync(d_out, pSlots, (size_t)B_ * KSLOT_ * DIM_ * sizeof(float),
                    cudaMemcpyDeviceToDevice, 0);
}

// round 15
// speedup vs baseline: 1.2572x; 1.2572x over previous
#include <cuda_runtime.h>
#include <cuda_bf16.h>
#include <math.h>
#include <stdint.h>

// ---------------- problem constants ----------------
#define B_     32
#define N_     4096
#define F_     768
#define DIM_   256
#define H_     4
#define DH_    64
#define KSLOT_ 16
#define IH_    64
#define ITERS_ 3
#define EPSW_  1e-8f
#define SCALE_ 0.125f

// ---------------- scratch (device globals; no allocation) ----------------
__device__ __nv_bfloat16 g_xhi[100663296];   // [131072][768]
__device__ __nv_bfloat16 g_xlo[100663296];
__device__ __nv_bfloat16 g_wb_hi[393216];    // [512][768]
__device__ __nv_bfloat16 g_wb_lo[393216];
__device__ float g_k [33554432];             // [131072][256]
__device__ float g_v [33554432];
__device__ float g_vsum[B_*DIM_];
__device__ float g_slots[B_*KSLOT_*DIM_];
__device__ float g_q    [B_*KSLOT_*DIM_];
__device__ float g_S    [B_*IH_];
__device__ float g_upd  [B_*IH_*DH_];

extern __shared__ float dynsm[];

// ---------------- PTX helpers ----------------
__device__ __forceinline__ uint32_t smem_u32(const void* p) {
    uint32_t a;
    asm("{ .reg .u64 t; cvta.to.shared.u64 t, %1; cvt.u32.u64 %0, t; }" : "=r"(a) : "l"(p));
    return a;
}
#define CP_ASYNC16(dst, src) \
    asm volatile("cp.async.cg.shared.global [%0], [%1], 16;" :: "r"(dst), "l"(src))
#define CP_COMMIT()  asm volatile("cp.async.commit_group;")
#define CP_WAIT0()   asm volatile("cp.async.wait_group 0;")
#define CP_WAIT1()   asm volatile("cp.async.wait_group 1;")

#define LDSM4(r0, r1, r2, r3, a) \
    asm volatile("ldmatrix.sync.aligned.m8n8.x4.shared.b16 {%0,%1,%2,%3}, [%4];" \
        : "=r"(r0), "=r"(r1), "=r"(r2), "=r"(r3) : "r"(a))

#define MMA16816(c, a, b) \
    asm volatile("mma.sync.aligned.m16n8k16.row.col.f32.bf16.bf16.f32 " \
        "{%0,%1,%2,%3}, {%4,%5,%6,%7}, {%8,%9}, {%0,%1,%2,%3};" \
        : "+f"((c)[0]), "+f"((c)[1]), "+f"((c)[2]), "+f"((c)[3]) \
        : "r"((a)[0]), "r"((a)[1]), "r"((a)[2]), "r"((a)[3]), "r"((b)[0]), "r"((b)[1]))

#define MMA_TF32(c, a, b) \
    asm volatile("mma.sync.aligned.m16n8k8.row.col.f32.tf32.tf32.f32 " \
        "{%0,%1,%2,%3}, {%4,%5,%6,%7}, {%8,%9}, {%0,%1,%2,%3};" \
        : "+f"((c)[0]), "+f"((c)[1]), "+f"((c)[2]), "+f"((c)[3]) \
        : "r"((a)[0]), "r"((a)[1]), "r"((a)[2]), "r"((a)[3]), "r"((b)[0]), "r"((b)[1]))

__device__ __forceinline__ void tf32split(float x, uint32_t& hi, uint32_t& lo) {
    asm("cvt.rna.tf32.f32 %0, %1;" : "=r"(hi) : "f"(x));
    float r = x - __uint_as_float(hi);
    asm("cvt.rna.tf32.f32 %0, %1;" : "=r"(lo) : "f"(r));
}

// ---------------- block reduce (256 threads) ----------------
__device__ __forceinline__ float2 blockReduceSum2(float a, float b) {
    __shared__ float sa[8], sb[8];
    int lane = threadIdx.x & 31, w = threadIdx.x >> 5;
#pragma unroll
    for (int o = 16; o; o >>= 1) {
        a += __shfl_down_sync(0xffffffffu, a, o);
        b += __shfl_down_sync(0xffffffffu, b, o);
    }
    if (lane == 0) { sa[w] = a; sb[w] = b; }
    __syncthreads();
    if (w == 0) {
        float aa = (lane < 8) ? sa[lane] : 0.f;
        float bb = (lane < 8) ? sb[lane] : 0.f;
#pragma unroll
        for (int o = 4; o; o >>= 1) {
            aa += __shfl_down_sync(0xffffffffu, aa, o);
            bb += __shfl_down_sync(0xffffffffu, bb, o);
        }
        if (lane == 0) { sa[0] = aa; sb[0] = bb; }
    }
    __syncthreads();
    float2 r = make_float2(sa[0], sb[0]);
    __syncthreads();
    return r;
}

// ---------------- K1: LayerNorm over 768 -> split bf16 hi/lo ----------------
__global__ __launch_bounds__(256) void ln_in_kernel(const float* __restrict__ x,
                                                    const float* __restrict__ g,
                                                    const float* __restrict__ bb) {
    size_t row = blockIdx.x;
    const float* xr = x + row * F_;
    int t = threadIdx.x;
    float v0 = xr[t], v1 = xr[t + 256], v2 = xr[t + 512];
    float2 r = blockReduceSum2(v0 + v1 + v2, v0 * v0 + v1 * v1 + v2 * v2);
    float mean = r.x * (1.f / 768.f);
    float var  = r.y * (1.f / 768.f) - mean * mean;
    float inv  = rsqrtf(var + 1e-5f);
    __nv_bfloat16* oh = g_xhi + row * F_;
    __nv_bfloat16* ol = g_xlo + row * F_;
#pragma unroll
    for (int e = 0; e < 3; e++) {
        int c = t + 256 * e;
        float vv = (e == 0 ? v0 : (e == 1 ? v1 : v2));
        float y = (vv - mean) * inv * g[c] + bb[c];
        __nv_bfloat16 h = __float2bfloat16(y);
        oh[c] = h;
        ol[c] = __float2bfloat16(y - __bfloat162float(h));
    }
}

// ---- wconv: weight split-convert + iter0 slot_q + zero vsum/S/upd ----
__global__ __launch_bounds__(256) void wconv_kernel(const float* __restrict__ Wk,
                                                    const float* __restrict__ Wv,
                                                    const float* __restrict__ lsg,
                                                    const float* __restrict__ lsb,
                                                    const float* __restrict__ Wq) {
    __shared__ float sn[256];
    int bidx = blockIdx.x, t = threadIdx.x;
#pragma unroll
    for (int e = 0; e < 3; e++) {
        int idx = bidx * 768 + e * 256 + t;
        float w = (idx < 196608) ? Wk[idx] : Wv[idx - 196608];
        __nv_bfloat16 h = __float2bfloat16(w);
        g_wb_hi[idx] = h;
        g_wb_lo[idx] = __float2bfloat16(w - __bfloat162float(h));
    }
    g_upd[bidx * 256 + t] = 0.f;
    if (t < 4) g_S[bidx * 4 + t] = 0.f;
    if (bidx < 32) g_vsum[bidx * 256 + t] = 0.f;

    float sv = g_slots[bidx * 256 + t];
    float2 r = blockReduceSum2(sv, sv * sv);
    float mean = r.x * (1.f / 256.f);
    float var  = r.y * (1.f / 256.f) - mean * mean;
    float inv  = rsqrtf(var + 1e-5f);
    sn[t] = (sv - mean) * inv * lsg[t] + lsb[t];
    __syncthreads();
    const float4* w4 = (const float4*)(Wq + (size_t)t * 256);
    float acc = 0.f;
#pragma unroll 8
    for (int c = 0; c < 64; c++) {
        float4 w = w4[c];
        acc += w.x * sn[4 * c] + w.y * sn[4 * c + 1] + w.z * sn[4 * c + 2] + w.w * sn[4 * c + 3];
    }
    g_q[bidx * 256 + t] = acc * SCALE_;
}

// ---------------- split-bf16 mma.sync projection GEMM ----------------
// BK=32, 3 stages of 32KB => 96KB smem, 2 CTAs/SM.
#define PSTG   32768
#define PROJ_SMEM (3 * PSTG)
#define SWZ32(row, c) ((row) * 64 + ((((c) ^ ((row) >> 1)) & 3) << 4))

__device__ __forceinline__ void proj_fill_async(uint32_t stg, int kt, size_t m0,
                                                int n0, int t) {
#pragma unroll
    for (int i = 0; i < 2; i++) {
        int idx = t + 256 * i;                 // 0..511 chunks of 16B
        int row = idx >> 2, c = idx & 3;
        uint32_t off = SWZ32(row, c);
        size_t aoff = ((m0 + row) * 768 + (size_t)kt * 32 + c * 8) * 2;
        size_t boff = (((size_t)(n0 + row)) * 768 + (size_t)kt * 32 + c * 8) * 2;
        CP_ASYNC16(stg + off,         (const char*)g_xhi   + aoff);
        CP_ASYNC16(stg + 8192 + off,  (const char*)g_xlo   + aoff);
        CP_ASYNC16(stg + 16384 + off, (const char*)g_wb_hi + boff);
        CP_ASYNC16(stg + 24576 + off, (const char*)g_wb_lo + boff);
    }
}

__global__ __launch_bounds__(256, 2) void proj_mma_kernel() {
    uint32_t base = smem_u32(dynsm);
    const int t = threadIdx.x;
    const int lane = t & 31, wid = t >> 5;
    const int wm = wid & 1, wn = wid >> 1;
    const int bx = blockIdx.x;
    const size_t m0 = (size_t)blockIdx.y * 128;
    const int n0 = bx * 128;

    float c[4][4][4];
#pragma unroll
    for (int mi = 0; mi < 4; mi++)
#pragma unroll
        for (int ni = 0; ni < 4; ni++)
#pragma unroll
            for (int e = 0; e < 4; e++) c[mi][ni][e] = 0.f;

    const int g = lane >> 3, rin = lane & 7;

    proj_fill_async(base, 0, m0, n0, t);
    CP_COMMIT();
    proj_fill_async(base + PSTG, 1, m0, n0, t);
    CP_COMMIT();

    for (int kt = 0; kt < 24; kt++) {
        if (kt + 2 < 24) CP_WAIT1(); else CP_WAIT0();
        __syncthreads();
        if (kt + 2 < 24) {
            proj_fill_async(base + (uint32_t)((kt + 2) % 3) * PSTG, kt + 2, m0, n0, t);
            CP_COMMIT();
        }
        uint32_t cur = base + (uint32_t)(kt % 3) * PSTG;

#pragma unroll
        for (int ks = 0; ks < 2; ks++) {
            uint32_t aHi[4][4], aLo[4][4], bHi[4][2], bLo[4][2];
#pragma unroll
            for (int mi = 0; mi < 4; mi++) {
                int row = wm * 64 + mi * 16 + (g & 1) * 8 + rin;
                int cc = ks * 2 + (g >> 1);
                uint32_t ad = cur + SWZ32(row, cc);
                LDSM4(aHi[mi][0], aHi[mi][1], aHi[mi][2], aHi[mi][3], ad);
                LDSM4(aLo[mi][0], aLo[mi][1], aLo[mi][2], aLo[mi][3], ad + 8192);
            }
#pragma unroll
            for (int bi = 0; bi < 2; bi++) {
                int nr = wn * 32 + bi * 16 + (g >> 1) * 8 + rin;
                int cc = ks * 2 + (g & 1);
                uint32_t bd = cur + 16384 + SWZ32(nr, cc);
                uint32_t r0, r1, r2, r3;
                LDSM4(r0, r1, r2, r3, bd);
                bHi[bi * 2][0] = r0; bHi[bi * 2][1] = r1;
                bHi[bi * 2 + 1][0] = r2; bHi[bi * 2 + 1][1] = r3;
                LDSM4(r0, r1, r2, r3, bd + 8192);
                bLo[bi * 2][0] = r0; bLo[bi * 2][1] = r1;
                bLo[bi * 2 + 1][0] = r2; bLo[bi * 2 + 1][1] = r3;
            }
#pragma unroll
            for (int mi = 0; mi < 4; mi++)
#pragma unroll
                for (int ni = 0; ni < 4; ni++) {
                    MMA16816(c[mi][ni], aHi[mi], bHi[ni]);
                    MMA16816(c[mi][ni], aHi[mi], bLo[ni]);
                    MMA16816(c[mi][ni], aLo[mi], bHi[ni]);
                }
        }
    }

    // epilogue: direct STG (float2 per row-half)
    float* outp = (bx < 2) ? g_k : g_v;
    int cb = (bx & 1) * 128 + wn * 32 + (lane & 3) * 2;
#pragma unroll
    for (int mi = 0; mi < 4; mi++) {
        size_t r0 = m0 + wm * 64 + mi * 16 + (lane >> 2);
#pragma unroll
        for (int ni = 0; ni < 4; ni++) {
            int col = cb + ni * 8;
            *(float2*)&outp[r0 * 256 + col]       = make_float2(c[mi][ni][0], c[mi][ni][1]);
            *(float2*)&outp[(r0 + 8) * 256 + col] = make_float2(c[mi][ni][2], c[mi][ni][3]);
        }
    }

    // fused vsum for V tiles
    if (bx >= 2) {
        int b = (int)(m0 >> 12);
#pragma unroll
        for (int ni = 0; ni < 4; ni++) {
            float s0 = 0.f, s1 = 0.f;
#pragma unroll
            for (int mi = 0; mi < 4; mi++) {
                s0 += c[mi][ni][0] + c[mi][ni][2];
                s1 += c[mi][ni][1] + c[mi][ni][3];
            }
#pragma unroll
            for (int o = 16; o >= 4; o >>= 1) {
                s0 += __shfl_down_sync(0xffffffffu, s0, o);
                s1 += __shfl_down_sync(0xffffffffu, s1, o);
            }
            if (lane < 4) {
                int col = (bx & 1) * 128 + wn * 32 + lane * 2 + ni * 8;
                atomicAdd(&g_vsum[b * 256 + col], s0);
                atomicAdd(&g_vsum[b * 256 + col + 1], s1);
            }
        }
    }
}

// ---------------- fused attention: tf32-MMA dots + softmax + S + tf32-MMA updates ----
#define NJ_ 32
#define ATTN_SMEM ((64 * 68 + NJ_ * 260 + NJ_ * 68 + 256) * 4)
__global__ __launch_bounds__(256, 3) void attn_kernel(float* __restrict__ attn_out) {
    float* qs  = dynsm;                        // [64 ih][68]
    float* kv  = dynsm + 64 * 68;              // [32 j][260]
    float* dsT = kv + NJ_ * 260;               // [32 j][68 ih]
    float* red = dsT + NJ_ * 68;
    int b = blockIdx.y, jt = blockIdx.x, t = threadIdx.x;
    int lane = t & 31, wid = t >> 5;
    int grp4 = lane >> 2, tg4 = lane & 3;

    for (int idx = t; idx < 4096; idx += 256) {
        int i = idx >> 8, c = idx & 255;
        qs[(i * 4 + (c >> 6)) * 68 + (c & 63)] = g_q[(b * KSLOT_ + i) * 256 + c];
    }
    const float4* kb = (const float4*)(g_k + ((size_t)b * N_ + jt * NJ_) * DIM_);
    for (int idx = t; idx < NJ_ * 64; idx += 256)
        ((float4*)(kv + (idx >> 6) * 260))[idx & 63] = kb[idx];
    __syncthreads();

    // dots via tf32 split MMA
    {
        int h = wid >> 1, jh = wid & 1;
        float c[2][4];
#pragma unroll
        for (int f = 0; f < 2; f++)
#pragma unroll
            for (int e = 0; e < 4; e++) c[f][e] = 0.f;

#pragma unroll
        for (int k8 = 0; k8 < 8; k8++) {
            int d0 = k8 * 8 + tg4;
            float a0f = qs[(grp4 * 4 + h) * 68 + d0];
            float a1f = qs[((grp4 + 8) * 4 + h) * 68 + d0];
            float a2f = qs[(grp4 * 4 + h) * 68 + d0 + 4];
            float a3f = qs[((grp4 + 8) * 4 + h) * 68 + d0 + 4];
            uint32_t ah[4], al[4];
            tf32split(a0f, ah[0], al[0]);
            tf32split(a1f, ah[1], al[1]);
            tf32split(a2f, ah[2], al[2]);
            tf32split(a3f, ah[3], al[3]);
#pragma unroll
            for (int n8 = 0; n8 < 2; n8++) {
                int j0 = jh * 16 + n8 * 8 + grp4;
                float b0f = kv[j0 * 260 + h * 64 + k8 * 8 + tg4];
                float b1f = kv[j0 * 260 + h * 64 + k8 * 8 + tg4 + 4];
                uint32_t bh[2], bl[2];
                tf32split(b0f, bh[0], bl[0]);
                tf32split(b1f, bh[1], bl[1]);
                MMA_TF32(c[n8], ah, bh);
                MMA_TF32(c[n8], ah, bl);
                MMA_TF32(c[n8], al, bh);
            }
        }
#pragma unroll
        for (int n8 = 0; n8 < 2; n8++) {
            int jb = jh * 16 + n8 * 8 + tg4 * 2;
            dsT[jb * 68 + grp4 * 4 + h]             = c[n8][0];
            dsT[(jb + 1) * 68 + grp4 * 4 + h]       = c[n8][1];
            dsT[jb * 68 + (grp4 + 8) * 4 + h]       = c[n8][2];
            dsT[(jb + 1) * 68 + (grp4 + 8) * 4 + h] = c[n8][3];
        }
    }
    __syncthreads();

    // joint softmax per column j
    {
        int j = t & 31, grp = t >> 5;
        float* row = dsT + j * 68 + grp * 8;
        float mx = -1e30f;
#pragma unroll
        for (int k2 = 0; k2 < 8; k2++) mx = fmaxf(mx, row[k2]);
        red[grp * 32 + j] = mx;
        __syncthreads();
        mx = red[j];
#pragma unroll
        for (int g2 = 1; g2 < 8; g2++) mx = fmaxf(mx, red[g2 * 32 + j]);
        __syncthreads();
        float sum = 0.f;
#pragma unroll
        for (int k2 = 0; k2 < 8; k2++) {
            float e = expf(row[k2] - mx);
            row[k2] = e;
            sum += e;
        }
        red[grp * 32 + j] = sum;
        __syncthreads();
        sum = red[j];
#pragma unroll
        for (int g2 = 1; g2 < 8; g2++) sum += red[g2 * 32 + j];
        float inv = 1.f / sum;
#pragma unroll
        for (int k2 = 0; k2 < 8; k2++) row[k2] *= inv;
    }
    __syncthreads();

    // S row sums -> atomic
    {
        int ih2 = t & 63, jq = t >> 6;
        float s = 0.f;
#pragma unroll
        for (int k2 = 0; k2 < 8; k2++) s += dsT[(jq * 8 + k2) * 68 + ih2];
        red[jq * 64 + ih2] = s;
    }
    __syncthreads();
    if (t < 64) atomicAdd(&g_S[b * IH_ + t], red[t] + red[64 + t] + red[128 + t] + red[192 + t]);

    if (attn_out) {
        for (int idx = t; idx < 512; idx += 256) {
            int i2 = idx >> 5, jl = idx & 31;
            float4 vv = *(const float4*)(dsT + jl * 68 + i2 * 4);
            attn_out[((size_t)b * KSLOT_ + i2) * N_ + jt * NJ_ + jl] =
                0.25f * (vv.x + vv.y + vv.z + vv.w);
        }
    }
    __syncthreads();

    const float4* vb = (const float4*)(g_v + ((size_t)b * N_ + jt * NJ_) * DIM_);
    for (int idx = t; idx < NJ_ * 64; idx += 256)
        ((float4*)(kv + (idx >> 6) * 260))[idx & 63] = vb[idx];
    __syncthreads();

    // updates via tf32 split MMA
    {
        int h = wid >> 1, dh = wid & 1;
        float c[4][4];
#pragma unroll
        for (int f = 0; f < 4; f++)
#pragma unroll
            for (int e = 0; e < 4; e++) c[f][e] = 0.f;

#pragma unroll
        for (int k8 = 0; k8 < 4; k8++) {
            int j0 = k8 * 8 + tg4;
            float a0f = dsT[j0 * 68 + grp4 * 4 + h];
            float a1f = dsT[j0 * 68 + (grp4 + 8) * 4 + h];
            float a2f = dsT[(j0 + 4) * 68 + grp4 * 4 + h];
            float a3f = dsT[(j0 + 4) * 68 + (grp4 + 8) * 4 + h];
            uint32_t ah[4], al[4];
            tf32split(a0f, ah[0], al[0]);
            tf32split(a1f, ah[1], al[1]);
            tf32split(a2f, ah[2], al[2]);
            tf32split(a3f, ah[3], al[3]);
#pragma unroll
            for (int n8 = 0; n8 < 4; n8++) {
                int d = h * 64 + dh * 32 + n8 * 8 + grp4;
                float b0f = kv[j0 * 260 + d];
                float b1f = kv[(j0 + 4) * 260 + d];
                uint32_t bh[2], bl[2];
                tf32split(b0f, bh[0], bl[0]);
                tf32split(b1f, bh[1], bl[1]);
                MMA_TF32(c[n8], ah, bh);
                MMA_TF32(c[n8], ah, bl);
                MMA_TF32(c[n8], al, bh);
            }
        }
#pragma unroll
        for (int n8 = 0; n8 < 4; n8++) {
            int dcol = dh * 32 + n8 * 8 + tg4 * 2;
            size_t base0 = ((size_t)b * KSLOT_ + grp4) * 4 + h;
            size_t base8 = ((size_t)b * KSLOT_ + grp4 + 8) * 4 + h;
            atomicAdd(&g_upd[base0 * DH_ + dcol],     c[n8][0]);
            atomicAdd(&g_upd[base0 * DH_ + dcol + 1], c[n8][1]);
            atomicAdd(&g_upd[base8 * DH_ + dcol],     c[n8][2]);
            atomicAdd(&g_upd[base8 * DH_ + dcol + 1], c[n8][3]);
        }
    }
}

// ---------------- GRU (8 rows per block) ----------------
__global__ __launch_bounds__(256) void gru_kernel(const float* __restrict__ w_ih,
                                                  const float* __restrict__ w_hh,
                                                  const float* __restrict__ b_ih,
                                                  const float* __restrict__ b_hh) {
    __shared__ float u[8][256];
    __shared__ float hp[8][256];
    int row0 = blockIdx.x * 8, t = threadIdx.x;
    int b = row0 >> 4;
#pragma unroll
    for (int r = 0; r < 8; r++) {
        int row = row0 + r;
        int ih = (row & 15) * 4 + (t >> 6);
        float upd = g_upd[(b * IH_ + ih) * DH_ + (t & 63)];
        float Sv  = g_S[b * IH_ + ih];
        u[r][t]  = (upd + EPSW_ * g_vsum[b * 256 + t]) / (Sv + (float)N_ * EPSW_);
        hp[r][t] = g_slots[(size_t)row * 256 + t];
    }
    __syncthreads();

    float s0a[8], s1a[8], gi2[8], gh2[8];
#pragma unroll
    for (int r = 0; r < 8; r++) { s0a[r] = 0.f; s1a[r] = 0.f; gi2[r] = 0.f; gh2[r] = 0.f; }

    const float4* wi0 = (const float4*)(w_ih + (size_t)t * 256);
    const float4* wi1 = (const float4*)(w_ih + (size_t)(256 + t) * 256);
    const float4* wi2 = (const float4*)(w_ih + (size_t)(512 + t) * 256);
    const float4* wh0 = (const float4*)(w_hh + (size_t)t * 256);
    const float4* wh1 = (const float4*)(w_hh + (size_t)(256 + t) * 256);
    const float4* wh2 = (const float4*)(w_hh + (size_t)(512 + t) * 256);

    for (int c = 0; c < 64; c++) {
        float4 a0 = wi0[c], a1 = wi1[c], a2 = wi2[c];
        float4 h0 = wh0[c], h1v = wh1[c], h2 = wh2[c];
#pragma unroll
        for (int r = 0; r < 8; r++) {
            float4 uu = *(const float4*)&u[r][4 * c];
            float4 hh = *(const float4*)&hp[r][4 * c];
            s0a[r] += a0.x * uu.x + a0.y * uu.y + a0.z * uu.z + a0.w * uu.w
                    + h0.x * hh.x + h0.y * hh.y + h0.z * hh.z + h0.w * hh.w;
            s1a[r] += a1.x * uu.x + a1.y * uu.y + a1.z * uu.z + a1.w * uu.w
                    + h1v.x * hh.x + h1v.y * hh.y + h1v.z * hh.z + h1v.w * hh.w;
            gi2[r] += a2.x * uu.x + a2.y * uu.y + a2.z * uu.z + a2.w * uu.w;
            gh2[r] += h2.x * hh.x + h2.y * hh.y + h2.z * hh.z + h2.w * hh.w;
        }
    }
    float bi0 = b_ih[t] + b_hh[t];
    float bi1 = b_ih[256 + t] + b_hh[256 + t];
    float bi2 = b_ih[512 + t], bh2 = b_hh[512 + t];
#pragma unroll
    for (int r = 0; r < 8; r++) {
        float rg = 1.f / (1.f + expf(-(s0a[r] + bi0)));
        float z  = 1.f / (1.f + expf(-(s1a[r] + bi1)));
        float n  = tanhf(gi2[r] + bi2 + rg * (gh2[r] + bh2));
        g_slots[(size_t)(row0 + r) * 256 + t] = (1.f - z) * n + z * hp[r][t];
    }
}

// ---------------- FF (8 rows per block) + next-iter slot_q + zeroing ----------------
__global__ __launch_bounds__(256) void ff_kernel(const float* __restrict__ g,
                                                 const float* __restrict__ bb,
                                                 const float* __restrict__ W1,
                                                 const float* __restrict__ b1,
                                                 const float* __restrict__ W2,
                                                 const float* __restrict__ b2,
                                                 const float* __restrict__ lsg,
                                                 const float* __restrict__ lsb,
                                                 const float* __restrict__ Wq,
                                                 int doq) {
    __shared__ float h1[8][256];
    __shared__ float a_s[8][1024];
    int row0 = blockIdx.x * 8, t = threadIdx.x;
    int w = t >> 5, l = t & 31;

    {
        int row = row0 + w;
        const float* sp = g_slots + (size_t)row * 256;
        float4 x0 = *(const float4*)(sp + l * 8);
        float4 x1 = *(const float4*)(sp + l * 8 + 4);
        float s = x0.x + x0.y + x0.z + x0.w + x1.x + x1.y + x1.z + x1.w;
        float q = x0.x * x0.x + x0.y * x0.y + x0.z * x0.z + x0.w * x0.w
                + x1.x * x1.x + x1.y * x1.y + x1.z * x1.z + x1.w * x1.w;
#pragma unroll
        for (int o = 16; o; o >>= 1) {
            s += __shfl_xor_sync(0xffffffffu, s, o);
            q += __shfl_xor_sync(0xffffffffu, q, o);
        }
        float mean = s * (1.f / 256.f);
        float var  = q * (1.f / 256.f) - mean * mean;
        float inv  = rsqrtf(var + 1e-5f);
        int c0 = l * 8;
        float xv[8] = {x0.x, x0.y, x0.z, x0.w, x1.x, x1.y, x1.z, x1.w};
#pragma unroll
        for (int e = 0; e < 8; e++)
            h1[w][c0 + e] = (xv[e] - mean) * inv * g[c0 + e] + bb[c0 + e];
    }
    __syncthreads();

    float acc[4][8];
#pragma unroll
    for (int m = 0; m < 4; m++)
#pragma unroll
        for (int r = 0; r < 8; r++) acc[m][r] = 0.f;

    const float4* w1p0 = (const float4*)(W1 + (size_t)t * 256);
    const float4* w1p1 = (const float4*)(W1 + (size_t)(t + 256) * 256);
    const float4* w1p2 = (const float4*)(W1 + (size_t)(t + 512) * 256);
    const float4* w1p3 = (const float4*)(W1 + (size_t)(t + 768) * 256);
    for (int c = 0; c < 64; c++) {
        float4 wv0 = w1p0[c], wv1 = w1p1[c], wv2 = w1p2[c], wv3 = w1p3[c];
#pragma unroll
        for (int r = 0; r < 8; r++) {
            float4 hh = *(const float4*)&h1[r][4 * c];
            acc[0][r] += wv0.x * hh.x + wv0.y * hh.y + wv0.z * hh.z + wv0.w * hh.w;
            acc[1][r] += wv1.x * hh.x + wv1.y * hh.y + wv1.z * hh.z + wv1.w * hh.w;
            acc[2][r] += wv2.x * hh.x + wv2.y * hh.y + wv2.z * hh.z + wv2.w * hh.w;
            acc[3][r] += wv3.x * hh.x + wv3.y * hh.y + wv3.z * hh.z + wv3.w * hh.w;
        }
    }
#pragma unroll
    for (int m = 0; m < 4; m++) {
        float bv = b1[m * 256 + t];
#pragma unroll
        for (int r = 0; r < 8; r++) {
            float v = acc[m][r] + bv;
            a_s[r][m * 256 + t] = 0.5f * v * (1.f + erff(v * 0.70710678118654752f));
        }
    }
    __syncthreads();

    float o[8];
#pragma unroll
    for (int r = 0; r < 8; r++) o[r] = 0.f;
    const float4* w2p = (const float4*)(W2 + (size_t)t * 1024);
    for (int c = 0; c < 256; c++) {
        float4 wv = w2p[c];
#pragma unroll
        for (int r = 0; r < 8; r++) {
            float4 aa = *(const float4*)&a_s[r][4 * c];
            o[r] += wv.x * aa.x + wv.y * aa.y + wv.z * aa.z + wv.w * aa.w;
        }
    }
    float bt = b2[t];
    __syncthreads();
#pragma unroll
    for (int r = 0; r < 8; r++) {
        float fin = g_slots[(size_t)(row0 + r) * 256 + t] + o[r] + bt;
        g_slots[(size_t)(row0 + r) * 256 + t] = fin;
        a_s[r][t] = fin;
    }
    __syncthreads();

    if (doq) {
        {
            float4 x0 = *(const float4*)&a_s[w][l * 8];
            float4 x1 = *(const float4*)&a_s[w][l * 8 + 4];
            float s = x0.x + x0.y + x0.z + x0.w + x1.x + x1.y + x1.z + x1.w;
            float q = x0.x * x0.x + x0.y * x0.y + x0.z * x0.z + x0.w * x0.w
                    + x1.x * x1.x + x1.y * x1.y + x1.z * x1.z + x1.w * x1.w;
#pragma unroll
            for (int oo = 16; oo; oo >>= 1) {
                s += __shfl_xor_sync(0xffffffffu, s, oo);
                q += __shfl_xor_sync(0xffffffffu, q, oo);
            }
            float mean = s * (1.f / 256.f);
            float var  = q * (1.f / 256.f) - mean * mean;
            float inv  = rsqrtf(var + 1e-5f);
            int c0 = l * 8;
            float xv[8] = {x0.x, x0.y, x0.z, x0.w, x1.x, x1.y, x1.z, x1.w};
#pragma unroll
            for (int e = 0; e < 8; e++)
                h1[w][c0 + e] = (xv[e] - mean) * inv * lsg[c0 + e] + lsb[c0 + e];
        }
        __syncthreads();

        float qa[8];
#pragma unroll
        for (int r = 0; r < 8; r++) qa[r] = 0.f;
        const float4* wq4 = (const float4*)(Wq + (size_t)t * 256);
        for (int c = 0; c < 64; c++) {
            float4 wv = wq4[c];
#pragma unroll
            for (int r = 0; r < 8; r++) {
                float4 ss = *(const float4*)&h1[r][4 * c];
                qa[r] += wv.x * ss.x + wv.y * ss.y + wv.z * ss.z + wv.w * ss.w;
            }
        }
#pragma unroll
        for (int r = 0; r < 8; r++)
            g_q[(size_t)(row0 + r) * 256 + t] = qa[r] * SCALE_;

#pragma unroll
        for (int e = 0; e < 8; e++)
            g_upd[blockIdx.x * 2048 + e * 256 + t] = 0.f;
        if (t < 32) g_S[blockIdx.x * 32 + t] = 0.f;
    }
}

// ---------------- launch ----------------
extern "C" void kernel_launch(void* const* d_in, const int* in_sizes, int n_in,
                              void* d_out, int out_size) {
    const float* inputs  = (const float*)d_in[0];
    const float* cond    = (const float*)d_in[1];
    const float* to_q_w  = (const float*)d_in[2];
    const float* to_k_w  = (const float*)d_in[3];
    const float* to_v_w  = (const float*)d_in[4];
    const float* w_ih    = (const float*)d_in[5];
    const float* w_hh    = (const float*)d_in[6];
    const float* b_ih    = (const float*)d_in[7];
    const float* b_hh    = (const float*)d_in[8];
    const float* ln_in_g = (const float*)d_in[9];
    const float* ln_in_b = (const float*)d_in[10];
    const float* ln_s_g  = (const float*)d_in[11];
    const float* ln_s_b  = (const float*)d_in[12];
    const float* ff_g    = (const float*)d_in[13];
    const float* ff_b    = (const float*)d_in[14];
    const float* ff_w1   = (const float*)d_in[15];
    const float* ff_b1   = (const float*)d_in[16];
    const float* ff_w2   = (const float*)d_in[17];
    const float* ff_b2   = (const float*)d_in[18];

    float* out_slots = (float*)d_out;
    float* out_attn  = out_slots + (size_t)B_ * KSLOT_ * DIM_;

    void* pSlots = nullptr;
    cudaGetSymbolAddress(&pSlots, g_slots);

    cudaFuncSetAttribute(attn_kernel, cudaFuncAttributeMaxDynamicSharedMemorySize, ATTN_SMEM);
    cudaFuncSetAttribute(proj_mma_kernel, cudaFuncAttributeMaxDynamicSharedMemorySize, PROJ_SMEM);

    cudaMemcpyAsync(pSlots, cond, (size_t)B_ * KSLOT_ * DIM_ * sizeof(float),
                    cudaMemcpyDeviceToDevice, 0);

    // 4th kernel = proj_mma (ncu capture target)
    ln_in_kernel<<<B_ * N_, 256>>>(inputs, ln_in_g, ln_in_b);                 // 1
    wconv_kernel<<<512, 256>>>(to_k_w, to_v_w, ln_s_g, ln_s_b, to_q_w);       // 2+3 combined? keep order
    proj_mma_kernel<<<dim3(4, 1024), 256, PROJ_SMEM>>>();                     // 3

    for (int it = 0; it < ITERS_; it++) {
        attn_kernel<<<dim3(128, B_), 256, ATTN_SMEM>>>(it == ITERS_ - 1 ? out_attn : (float*)nullptr);
        gru_kernel<<<64, 256>>>(w_ih, w_hh, b_ih, b_hh);
        ff_kernel<<<64, 256>>>(ff_g, ff_b, ff_w1, ff_b1, ff_w2, ff_b2,
                               ln_s_g, ln_s_b, to_q_w, it < ITERS_ - 1 ? 1 : 0);
    }
    cudaMemcpyAsync(d_out, pSlots, (size_t)B_ * KSLOT_ * DIM_ * sizeof(float),
                    cudaMemcpyDeviceToDevice, 0);
}